// round 1
// baseline (speedup 1.0000x reference)
#include <cuda_runtime.h>

// ---------------------------------------------------------------------------
// EGNN layer, fused fp32 implementation.
//   Inputs (metadata order):
//    0 h[N,128] 1 x[N,3] 2 edge_attr[E,1] 3 v_init[N,3] 4 edge_index[2,E](int)
//    5 edge_W1[258,128] 6 edge_b1[128] 7 edge_W2[128,128] 8 edge_b2[128]
//    9 coord_W1[128,128] 10 coord_b1[128] 11 coord_W2[128,1]
//   12 inf_W1[128,64] 13 inf_b1[64] 14 inf_W2[64,1] 15 inf_b2[1]
//   16 node_W1[256,128] 17 node_b1[128] 18 node_W2[128,128] 19 node_b2[128]
//   20 vel_W1[128,128] 21 vel_b1[128] 22 vel_W2[128,1]
//   Output: concat(h_out[N,128], x_out[N,3], v_out[N,3]) as fp32.
// ---------------------------------------------------------------------------

#define TE   64      // edges (or nodes) per CTA
#define LDA  132     // smem row stride (floats): 16B-aligned rows, conflict-free A loads
#define S1LD 65      // stride for the [64,64] inf hidden tile
#define MAXN 50016   // static scratch capacity (N = 50000 in this problem)

__device__ float  g_mi[(size_t)MAXN * 128];   // segment-sum of e_ij * m_ij
__device__ float4 g_agg[MAXN];                // xyz: segment-sum of x_update, w: degree

// shared memory carve (floats)
#define OFF_A  0
#define OFF_B  (TE * LDA)            //  8448
#define OFF_C  (2 * TE * LDA)        // 16896
#define OFF_W  (3 * TE * LDA)        // 25344 : weight staging tile, 8x128
#define OFF_X  (OFF_W + 8 * 128)     // 26368 : per-edge scalars [64][8]
#define OFF_R  (OFF_X + TE * 8)      // 26880 : row idx [64]
#define OFF_CC (OFF_R + TE)          // 26944 : col idx [64]
#define SMEM_FLOATS (OFF_CC + TE)    // 27008
#define SMEM_BYTES  (SMEM_FLOATS * 4)  // 108032 bytes -> 2 CTAs / SM

__device__ __forceinline__ float siluf(float v) {
    return v * (1.0f / (1.0f + __expf(-v)));
}

__device__ __forceinline__ void init_acc(float acc[4][8], const float* __restrict__ bias, int tx) {
    float4 b0 = __ldg((const float4*)bias + tx * 2);
    float4 b1 = __ldg((const float4*)bias + tx * 2 + 1);
#pragma unroll
    for (int i = 0; i < 4; ++i) {
        acc[i][0] = b0.x; acc[i][1] = b0.y; acc[i][2] = b0.z; acc[i][3] = b0.w;
        acc[i][4] = b1.x; acc[i][5] = b1.y; acc[i][6] = b1.z; acc[i][7] = b1.w;
    }
}

// C[64,128] += A[64,K] @ W[K,128]; A in smem (stride LDA), W in global (row-major).
// 256 threads = 16 (ty: 4 rows each) x 16 (tx: 8 cols each). Leading __syncthreads
// of each K-tile doubles as the stage barrier for the caller.
__device__ __forceinline__ void gemm_acc(float acc[4][8], const float* __restrict__ As,
                                         const float* __restrict__ Wg, int K,
                                         float* wt, int tid, int ty, int tx) {
    for (int k0 = 0; k0 < K; k0 += 8) {
        __syncthreads();
        ((float4*)wt)[tid] = __ldg((const float4*)(Wg + k0 * 128) + tid);
        __syncthreads();
        const float* ap = As + (ty * 4) * LDA + k0;
#pragma unroll
        for (int k = 0; k < 8; ++k) {
            float a0 = ap[k];
            float a1 = ap[LDA + k];
            float a2 = ap[2 * LDA + k];
            float a3 = ap[3 * LDA + k];
            float4 b0 = *(const float4*)(wt + k * 128 + tx * 8);
            float4 b1 = *(const float4*)(wt + k * 128 + tx * 8 + 4);
            float b[8] = {b0.x, b0.y, b0.z, b0.w, b1.x, b1.y, b1.z, b1.w};
            float a[4] = {a0, a1, a2, a3};
#pragma unroll
            for (int i = 0; i < 4; ++i)
#pragma unroll
                for (int j = 0; j < 8; ++j)
                    acc[i][j] += a[i] * b[j];
        }
    }
}

// C[64,64] += A[64,K] @ W[K,64]; threads = 32 (ty2: 2 rows) x 8 (tx2: 8 cols)
__device__ __forceinline__ void gemm_acc64(float acc[2][8], const float* __restrict__ As,
                                           const float* __restrict__ Wg, int K,
                                           float* wt, int tid, int ty2, int tx2) {
    for (int k0 = 0; k0 < K; k0 += 8) {
        __syncthreads();
        if (tid < 128)
            ((float4*)wt)[tid] = __ldg((const float4*)(Wg + k0 * 64) + tid);
        __syncthreads();
        const float* ap = As + (ty2 * 2) * LDA + k0;
#pragma unroll
        for (int k = 0; k < 8; ++k) {
            float a0 = ap[k];
            float a1 = ap[LDA + k];
            float4 b0 = *(const float4*)(wt + k * 64 + tx2 * 8);
            float4 b1 = *(const float4*)(wt + k * 64 + tx2 * 8 + 4);
            float b[8] = {b0.x, b0.y, b0.z, b0.w, b1.x, b1.y, b1.z, b1.w};
#pragma unroll
            for (int j = 0; j < 8; ++j) {
                acc[0][j] += a0 * b[j];
                acc[1][j] += a1 * b[j];
            }
        }
    }
}

template <bool ACT>
__device__ __forceinline__ void store_tile(const float acc[4][8], float* C, int ty, int tx) {
#pragma unroll
    for (int i = 0; i < 4; ++i) {
        float4 v0, v1;
        v0.x = ACT ? siluf(acc[i][0]) : acc[i][0];
        v0.y = ACT ? siluf(acc[i][1]) : acc[i][1];
        v0.z = ACT ? siluf(acc[i][2]) : acc[i][2];
        v0.w = ACT ? siluf(acc[i][3]) : acc[i][3];
        v1.x = ACT ? siluf(acc[i][4]) : acc[i][4];
        v1.y = ACT ? siluf(acc[i][5]) : acc[i][5];
        v1.z = ACT ? siluf(acc[i][6]) : acc[i][6];
        v1.w = ACT ? siluf(acc[i][7]) : acc[i][7];
        float* p = C + (ty * 4 + i) * LDA + tx * 8;
        *(float4*)p = v0;
        *(float4*)(p + 4) = v1;
    }
}

__global__ void egnn_zero_kernel(int N) {
    int total = N * 32;  // float4 count of g_mi
    for (int i = blockIdx.x * blockDim.x + threadIdx.x; i < total + N;
         i += gridDim.x * blockDim.x) {
        if (i < total)
            ((float4*)g_mi)[i] = make_float4(0.f, 0.f, 0.f, 0.f);
        else
            g_agg[i - total] = make_float4(0.f, 0.f, 0.f, 0.f);
    }
}

__global__ void __launch_bounds__(256, 2)
egnn_edge_kernel(const float* __restrict__ h, const float* __restrict__ x,
                 const float* __restrict__ eattr, const int* __restrict__ ei,
                 int E, int N,
                 const float* __restrict__ eW1, const float* __restrict__ eb1,
                 const float* __restrict__ eW2, const float* __restrict__ eb2,
                 const float* __restrict__ cW1, const float* __restrict__ cb1,
                 const float* __restrict__ cW2,
                 const float* __restrict__ iW1, const float* __restrict__ ib1,
                 const float* __restrict__ iW2, const float* __restrict__ ib2) {
    extern __shared__ float sm[];
    float* bufA = sm + OFF_A;   // h[row] tile -> later m_ij
    float* bufB = sm + OFF_B;   // h[col] tile -> later s1 (inf hidden)
    float* bufC = sm + OFF_C;   // m1 -> later c1 (coord hidden)
    float* wt   = sm + OFF_W;
    float* xda  = sm + OFF_X;   // [64][8]: dx,dy,dz,dist,attr,e,phi,valid
    int* ridx = (int*)(sm + OFF_R);
    int* cidx = (int*)(sm + OFF_CC);

    const int tid = threadIdx.x;
    const int tx = tid & 15, ty = tid >> 4;
    const int e0 = blockIdx.x * TE;

    if (tid < TE) {
        int e = e0 + tid;
        int r = 0, c = 0;
        float at = 0.f, valid = 0.f;
        if (e < E) { r = ei[e]; c = ei[E + e]; at = eattr[e]; valid = 1.f; }
        float dx = x[r * 3 + 0] - x[c * 3 + 0];
        float dy = x[r * 3 + 1] - x[c * 3 + 1];
        float dz = x[r * 3 + 2] - x[c * 3 + 2];
        xda[tid * 8 + 0] = dx; xda[tid * 8 + 1] = dy; xda[tid * 8 + 2] = dz;
        xda[tid * 8 + 3] = dx * dx + dy * dy + dz * dz;
        xda[tid * 8 + 4] = at;
        xda[tid * 8 + 7] = valid;
        ridx[tid] = r; cidx[tid] = c;
    }
    __syncthreads();

    // gather h[row], h[col] tiles (L2 hits: h is 25.6MB, L2-resident)
    for (int q = tid; q < TE * 32; q += 256) {
        int t = q >> 5, k4 = q & 31;
        int r = ridx[t], c = cidx[t];
        ((float4*)(bufA + t * LDA))[k4] = __ldg((const float4*)h + r * 32 + k4);
        ((float4*)(bufB + t * LDA))[k4] = __ldg((const float4*)h + c * 32 + k4);
    }
    // gemm_acc's leading __syncthreads covers the gather

    float acc[4][8];

    // ---- m1 = silu(ef @ edge_W1 + b1), K = 258 ----
    init_acc(acc, eb1, tx);
    gemm_acc(acc, bufA, eW1, 128, wt, tid, ty, tx);
    gemm_acc(acc, bufB, eW1 + 128 * 128, 128, wt, tid, ty, tx);
    {   // K tail: rows 256 (dist_sq), 257 (edge_attr)
        float4 wa0 = __ldg((const float4*)(eW1 + 256 * 128) + tx * 2);
        float4 wa1 = __ldg((const float4*)(eW1 + 256 * 128) + tx * 2 + 1);
        float4 wb0 = __ldg((const float4*)(eW1 + 257 * 128) + tx * 2);
        float4 wb1 = __ldg((const float4*)(eW1 + 257 * 128) + tx * 2 + 1);
#pragma unroll
        for (int i = 0; i < 4; ++i) {
            float d = xda[(ty * 4 + i) * 8 + 3];
            float a = xda[(ty * 4 + i) * 8 + 4];
            acc[i][0] += d * wa0.x + a * wb0.x;
            acc[i][1] += d * wa0.y + a * wb0.y;
            acc[i][2] += d * wa0.z + a * wb0.z;
            acc[i][3] += d * wa0.w + a * wb0.w;
            acc[i][4] += d * wa1.x + a * wb1.x;
            acc[i][5] += d * wa1.y + a * wb1.y;
            acc[i][6] += d * wa1.z + a * wb1.z;
            acc[i][7] += d * wa1.w + a * wb1.w;
        }
    }
    store_tile<true>(acc, bufC, ty, tx);   // m1

    // ---- m_ij = silu(m1 @ edge_W2 + b2) ----
    init_acc(acc, eb2, tx);
    gemm_acc(acc, bufC, eW2, 128, wt, tid, ty, tx);
    store_tile<true>(acc, bufA, ty, tx);   // m_ij (overwrites h[row] tile)

    // ---- s1 = silu(m_ij @ inf_W1 + inf_b1) : [64,64] ----
    {
        const int tx2 = tid & 7, ty2 = tid >> 3;
        float acc2[2][8];
        float4 b0 = __ldg((const float4*)ib1 + tx2 * 2);
        float4 b1 = __ldg((const float4*)ib1 + tx2 * 2 + 1);
        acc2[0][0] = b0.x; acc2[0][1] = b0.y; acc2[0][2] = b0.z; acc2[0][3] = b0.w;
        acc2[0][4] = b1.x; acc2[0][5] = b1.y; acc2[0][6] = b1.z; acc2[0][7] = b1.w;
#pragma unroll
        for (int j = 0; j < 8; ++j) acc2[1][j] = acc2[0][j];
        gemm_acc64(acc2, bufA, iW1, 128, wt, tid, ty2, tx2);
#pragma unroll
        for (int i = 0; i < 2; ++i)
#pragma unroll
            for (int j = 0; j < 8; ++j)
                bufB[(ty2 * 2 + i) * S1LD + tx2 * 8 + j] = siluf(acc2[i][j]);
    }

    // ---- c1 = silu(m_ij @ coord_W1 + coord_b1) ----
    init_acc(acc, cb1, tx);
    gemm_acc(acc, bufA, cW1, 128, wt, tid, ty, tx);
    store_tile<true>(acc, bufC, ty, tx);   // c1

    __syncthreads();
    if (tid < 64) wt[tid] = __ldg(iW2 + tid);
    if (tid >= 64 && tid < 192) wt[tid] = __ldg(cW2 + tid - 64);
    __syncthreads();

    // ---- e_ij, phi_x scalars ----
    if (tid < TE) {
        const float* srow = bufB + tid * S1LD;
        float s = __ldg(ib2);
#pragma unroll 8
        for (int k = 0; k < 64; ++k) s += srow[k] * wt[k];
        float ev = 1.f / (1.f + __expf(-s));
        const float* crow = bufC + tid * LDA;
        float p = 0.f;
#pragma unroll 8
        for (int k = 0; k < 128; ++k) p += crow[k] * wt[64 + k];
        xda[tid * 8 + 5] = ev;
        xda[tid * 8 + 6] = p;
    }
    __syncthreads();

    // ---- scatter: x_update + degree (one float4 atomic / edge) ----
    if (tid < TE && xda[tid * 8 + 7] != 0.f) {
        float ev = xda[tid * 8 + 5], p = xda[tid * 8 + 6];
        float s = ev * p;
        atomicAdd(&g_agg[ridx[tid]],
                  make_float4(s * xda[tid * 8 + 0], s * xda[tid * 8 + 1],
                              s * xda[tid * 8 + 2], 1.0f));
    }
    // ---- scatter: m_i += e_ij * m_ij (float4 vector atomics) ----
    for (int q = tid; q < TE * 32; q += 256) {
        int t = q >> 5, k4 = q & 31;
        if (xda[t * 8 + 7] != 0.f) {
            float ev = xda[t * 8 + 5];
            float4 m = ((float4*)(bufA + t * LDA))[k4];
            m.x *= ev; m.y *= ev; m.z *= ev; m.w *= ev;
            atomicAdd(((float4*)g_mi) + ridx[t] * 32 + k4, m);
        }
    }
}

__global__ void __launch_bounds__(256, 2)
egnn_node_kernel(const float* __restrict__ h, const float* __restrict__ x,
                 const float* __restrict__ vinit, int N,
                 const float* __restrict__ nW1, const float* __restrict__ nb1,
                 const float* __restrict__ nW2, const float* __restrict__ nb2,
                 const float* __restrict__ vW1, const float* __restrict__ vb1,
                 const float* __restrict__ vW2,
                 float* __restrict__ out_h, float* __restrict__ out_x,
                 float* __restrict__ out_v) {
    extern __shared__ float sm[];
    float* bufA = sm + OFF_A;   // h tile
    float* bufB = sm + OFF_B;   // m_i tile
    float* bufC = sm + OFF_C;   // t1 -> n1
    float* wt   = sm + OFF_W;

    const int tid = threadIdx.x;
    const int tx = tid & 15, ty = tid >> 4;
    const int n0 = blockIdx.x * TE;

    for (int q = tid; q < TE * 32; q += 256) {
        int t = q >> 5, k4 = q & 31;
        int n = n0 + t;
        if (n >= N) n = N - 1;
        ((float4*)(bufA + t * LDA))[k4] = __ldg((const float4*)h + n * 32 + k4);
        ((float4*)(bufB + t * LDA))[k4] = ((const float4*)g_mi)[n * 32 + k4];
    }

    float acc[4][8];

    // ---- t1 = silu(h @ vel_W1 + vel_b1) ----
    init_acc(acc, vb1, tx);
    gemm_acc(acc, bufA, vW1, 128, wt, tid, ty, tx);
    store_tile<true>(acc, bufC, ty, tx);
    __syncthreads();
    if (tid < 128) wt[tid] = __ldg(vW2 + tid);
    __syncthreads();

    // ---- vel_scale, v_out, x_out ----
    if (tid < TE) {
        int n = n0 + tid;
        if (n < N) {
            const float* trow = bufC + tid * LDA;
            float s = 0.f;
#pragma unroll 8
            for (int k = 0; k < 128; ++k) s += trow[k] * wt[k];
            float vx = vinit[n * 3 + 0] * s;
            float vy = vinit[n * 3 + 1] * s;
            float vz = vinit[n * 3 + 2] * s;
            out_v[n * 3 + 0] = vx; out_v[n * 3 + 1] = vy; out_v[n * 3 + 2] = vz;
            float4 ag = g_agg[n];
            float inv = 1.0f / (float)(N - 1);
            float x0 = x[n * 3 + 0], x1 = x[n * 3 + 1], x2 = x[n * 3 + 2];
            if (ag.w > 0.f) {
                out_x[n * 3 + 0] = x0 + vx + ag.x * inv;
                out_x[n * 3 + 1] = x1 + vy + ag.y * inv;
                out_x[n * 3 + 2] = x2 + vz + ag.z * inv;
            } else {
                out_x[n * 3 + 0] = x0;
                out_x[n * 3 + 1] = x1;
                out_x[n * 3 + 2] = x2;
            }
        }
    }

    // ---- n1 = silu([h, m_i] @ node_W1 + node_b1) ----
    init_acc(acc, nb1, tx);
    gemm_acc(acc, bufA, nW1, 128, wt, tid, ty, tx);
    gemm_acc(acc, bufB, nW1 + 128 * 128, 128, wt, tid, ty, tx);
    store_tile<true>(acc, bufC, ty, tx);

    // ---- h_out = n1 @ node_W2 + node_b2 ----
    init_acc(acc, nb2, tx);
    gemm_acc(acc, bufC, nW2, 128, wt, tid, ty, tx);
#pragma unroll
    for (int i = 0; i < 4; ++i) {
        int n = n0 + ty * 4 + i;
        if (n < N) {
            float4 v0 = make_float4(acc[i][0], acc[i][1], acc[i][2], acc[i][3]);
            float4 v1 = make_float4(acc[i][4], acc[i][5], acc[i][6], acc[i][7]);
            float4* p = (float4*)(out_h + (size_t)n * 128);
            p[tx * 2] = v0;
            p[tx * 2 + 1] = v1;
        }
    }
}

extern "C" void kernel_launch(void* const* d_in, const int* in_sizes, int n_in,
                              void* d_out, int out_size) {
    const float* h     = (const float*)d_in[0];
    const float* x     = (const float*)d_in[1];
    const float* eattr = (const float*)d_in[2];
    const float* vinit = (const float*)d_in[3];
    const int*   ei    = (const int*)d_in[4];
    const float* eW1 = (const float*)d_in[5];
    const float* eb1 = (const float*)d_in[6];
    const float* eW2 = (const float*)d_in[7];
    const float* eb2 = (const float*)d_in[8];
    const float* cW1 = (const float*)d_in[9];
    const float* cb1 = (const float*)d_in[10];
    const float* cW2 = (const float*)d_in[11];
    const float* iW1 = (const float*)d_in[12];
    const float* ib1 = (const float*)d_in[13];
    const float* iW2 = (const float*)d_in[14];
    const float* ib2 = (const float*)d_in[15];
    const float* nW1 = (const float*)d_in[16];
    const float* nb1 = (const float*)d_in[17];
    const float* nW2 = (const float*)d_in[18];
    const float* nb2 = (const float*)d_in[19];
    const float* vW1 = (const float*)d_in[20];
    const float* vb1 = (const float*)d_in[21];
    const float* vW2 = (const float*)d_in[22];

    int N = in_sizes[0] / 128;
    int E = in_sizes[2];

    float* out   = (float*)d_out;
    float* out_h = out;
    float* out_x = out + (size_t)N * 128;
    float* out_v = out_x + (size_t)N * 3;

    cudaFuncSetAttribute(egnn_edge_kernel,
                         cudaFuncAttributeMaxDynamicSharedMemorySize, SMEM_BYTES);
    cudaFuncSetAttribute(egnn_node_kernel,
                         cudaFuncAttributeMaxDynamicSharedMemorySize, SMEM_BYTES);

    egnn_zero_kernel<<<512, 256>>>(N);
    egnn_edge_kernel<<<(E + TE - 1) / TE, 256, SMEM_BYTES>>>(
        h, x, eattr, ei, E, N, eW1, eb1, eW2, eb2, cW1, cb1, cW2,
        iW1, ib1, iW2, ib2);
    egnn_node_kernel<<<(N + TE - 1) / TE, 256, SMEM_BYTES>>>(
        h, x, vinit, N, nW1, nb1, nW2, nb2, vW1, vb1, vW2,
        out_h, out_x, out_v);
}